// round 1
// baseline (speedup 1.0000x reference)
#include <cuda_runtime.h>

#define BATCH 16
#define CH    256
#define HH    64
#define WW    64
#define NPIX  (HH * WW)

// ---- packed f32x2 helpers (Blackwell FFMA2: only reachable via PTX) ----
__device__ __forceinline__ unsigned long long pk2(float lo, float hi) {
    unsigned long long r;
    asm("mov.b64 %0, {%1, %2};" : "=l"(r) : "f"(lo), "f"(hi));
    return r;
}
__device__ __forceinline__ void upk2(unsigned long long v, float &lo, float &hi) {
    asm("mov.b64 {%0, %1}, %2;" : "=f"(lo), "=f"(hi) : "l"(v));
}
__device__ __forceinline__ void ffma2(unsigned long long &d,
                                      unsigned long long a,
                                      unsigned long long b) {
    asm("fma.rn.f32x2 %0, %1, %2, %0;" : "+l"(d) : "l"(a), "l"(b));
}

// out[b, oi*9+oj, i, j] = (1/C) * sum_c x[b,c,i,j] * y[b,c,i+oi-4, j+oj-4]
// Thread: 8 consecutive j pixels (one j-group), one oi, all 9 oj.
// Block: 8 j-groups x 9 oi x 4 rows = 288 threads. Grid: (H/4, B).
__global__ __launch_bounds__(288, 1)
void corr_kernel(const float* __restrict__ x, const float* __restrict__ y,
                 float* __restrict__ out) {
    const int tid = threadIdx.x;
    const int tx  = tid & 7;          // j-group 0..7
    const int oi  = (tid >> 3) % 9;   // row displacement 0..8
    const int ty  = tid / 72;         // row within block 0..3
    const int b   = blockIdx.y;
    const int i   = blockIdx.x * 4 + ty;
    const int j0  = tx * 8;
    const int r   = i + oi - 4;       // displaced y row

    float* outp = out + (((size_t)b * 81 + (size_t)oi * 9) * HH + i) * WW + j0;

    // Whole displaced row out of range -> all 72 outputs are zero.
    if ((unsigned)r >= (unsigned)HH) {
        const float4 z = make_float4(0.f, 0.f, 0.f, 0.f);
        #pragma unroll
        for (int oj = 0; oj < 9; ++oj) {
            *(float4*)(outp + oj * NPIX)     = z;
            *(float4*)(outp + oj * NPIX + 4) = z;
        }
        return;
    }

    const float* xp = x + (size_t)b * CH * NPIX + i * WW + j0;
    const float* yp = y + (size_t)b * CH * NPIX + r * WW + (j0 - 4);
    const bool first = (tx == 0);   // window cols -4..-1 invalid
    const bool last  = (tx == 7);   // window cols 64..67 invalid

    unsigned long long acc[9][4];   // acc[oj][p] = packed (out[2p], out[2p+1])
    #pragma unroll
    for (int oj = 0; oj < 9; ++oj)
        #pragma unroll
        for (int p = 0; p < 4; ++p) acc[oj][p] = 0ull;

    #pragma unroll 2
    for (int c = 0; c < CH; ++c, xp += NPIX, yp += NPIX) {
        const float4 xa = *(const float4*)xp;
        const float4 xb = *(const float4*)(xp + 4);
        const float4 zz = make_float4(0.f, 0.f, 0.f, 0.f);
        const float4 y0 = first ? zz : *(const float4*)yp;          // cols j0-4..j0-1
        const float4 y1 = *(const float4*)(yp + 4);                 // cols j0..j0+3
        const float4 y2 = *(const float4*)(yp + 8);                 // cols j0+4..j0+7
        const float4 y3 = last  ? zz : *(const float4*)(yp + 12);   // cols j0+8..j0+11

        const float yw[16] = {y0.x, y0.y, y0.z, y0.w,  y1.x, y1.y, y1.z, y1.w,
                              y2.x, y2.y, y2.z, y2.w,  y3.x, y3.y, y3.z, y3.w};

        unsigned long long xq[4];
        xq[0] = pk2(xa.x, xa.y); xq[1] = pk2(xa.z, xa.w);
        xq[2] = pk2(xb.x, xb.y); xq[3] = pk2(xb.z, xb.w);

        // Sliding pairs of the y window: yq[k] = (yw[k], yw[k+1]), k = 0..14
        unsigned long long yq[15];
        #pragma unroll
        for (int k = 0; k < 15; ++k) yq[k] = pk2(yw[k], yw[k + 1]);

        // acc[oj][p] += (x[2p],x[2p+1]) * (yw[2p+oj], yw[2p+1+oj])
        #pragma unroll
        for (int oj = 0; oj < 9; ++oj)
            #pragma unroll
            for (int p = 0; p < 4; ++p)
                ffma2(acc[oj][p], xq[p], yq[2 * p + oj]);
    }

    const float s = 1.0f / (float)CH;
    #pragma unroll
    for (int oj = 0; oj < 9; ++oj) {
        float v[8];
        #pragma unroll
        for (int p = 0; p < 4; ++p) upk2(acc[oj][p], v[2 * p], v[2 * p + 1]);
        const float4 lo = make_float4(v[0] * s, v[1] * s, v[2] * s, v[3] * s);
        const float4 hi = make_float4(v[4] * s, v[5] * s, v[6] * s, v[7] * s);
        *(float4*)(outp + oj * NPIX)     = lo;
        *(float4*)(outp + oj * NPIX + 4) = hi;
    }
}

extern "C" void kernel_launch(void* const* d_in, const int* in_sizes, int n_in,
                              void* d_out, int out_size) {
    const float* x = (const float*)d_in[0];
    const float* y = (const float*)d_in[1];
    float* out = (float*)d_out;
    dim3 grid(HH / 4, BATCH);
    corr_kernel<<<grid, 288>>>(x, y, out);
}

// round 2
// speedup vs baseline: 1.0287x; 1.0287x over previous
#include <cuda_runtime.h>

#define BATCH 16
#define CH    256
#define HH    64
#define WW    64
#define NPIX  (HH * WW)

typedef unsigned long long u64;

// ---- packed f32x2 helpers (Blackwell FFMA2, PTX-only) ----
__device__ __forceinline__ u64 pk2(float lo, float hi) {
    u64 r;
    asm("mov.b64 %0, {%1, %2};" : "=l"(r) : "f"(lo), "f"(hi));
    return r;
}
__device__ __forceinline__ void upk2(u64 v, float &lo, float &hi) {
    asm("mov.b64 {%0, %1}, %2;" : "=f"(lo), "=f"(hi) : "l"(v));
}
__device__ __forceinline__ void ffma2(u64 &d, u64 a, u64 b) {
    asm("fma.rn.f32x2 %0, %1, %2, %0;" : "+l"(d) : "l"(a), "l"(b));
}

// out[b, oi*9+oj, i, j] = (1/C) * sum_c x[b,c,i,j] * y[b,c,i+oi-4, j+oj-4]
// Thread: 8 consecutive j (one group), one oi, all 9 oj.
// Accumulator packing by oj parity:
//   even oj: pixel pairs (0,1)(2,3)(4,5)(6,7)  -> y pair index even (reg-adjacent)
//   odd  oj: pixel pairs (1,2)(3,4)(5,6) + scalars j=0, j=7 -> y pair index even too
// => zero y re-packing MOVs; only 3 misaligned x packs.
// Block: 8 tx * 9 oi * 2 rows = 144 threads, 3 blocks/SM.
__global__ __launch_bounds__(144, 3)
void corr_kernel(const float* __restrict__ x, const float* __restrict__ y,
                 float* __restrict__ out) {
    const int tid = threadIdx.x;
    const int tx  = tid & 7;          // j-group 0..7
    const int oi  = (tid >> 3) % 9;   // row displacement 0..8
    const int ty  = tid / 72;         // row within block 0..1
    const int b   = blockIdx.y;
    const int i   = blockIdx.x * 2 + ty;
    const int j0  = tx * 8;
    const int r   = i + oi - 4;       // displaced y row

    float* outp = out + (((size_t)b * 81 + (size_t)oi * 9) * HH + i) * WW + j0;

    if ((unsigned)r >= (unsigned)HH) {   // whole displaced row OOB -> zeros
        const float4 z = make_float4(0.f, 0.f, 0.f, 0.f);
        #pragma unroll
        for (int oj = 0; oj < 9; ++oj) {
            *(float4*)(outp + oj * NPIX)     = z;
            *(float4*)(outp + oj * NPIX + 4) = z;
        }
        return;
    }

    const float* xp = x + (size_t)b * CH * NPIX + i * WW + j0;
    const float* yp = y + (size_t)b * CH * NPIX + r * WW + (j0 - 4);
    const bool first = (tx == 0);   // window cols -4..-1 invalid
    const bool last  = (tx == 7);   // window cols 64..67 invalid

    // Accumulators
    u64   ae[5][4];   // even oj=2e: pairs (2p,2p+1)
    u64   ao[4][3];   // odd  oj=2o+1: pairs (2p+1,2p+2)
    float s0[4];      // odd oj, pixel 0
    float s7[4];      // odd oj, pixel 7
    #pragma unroll
    for (int e = 0; e < 5; ++e)
        #pragma unroll
        for (int p = 0; p < 4; ++p) ae[e][p] = 0ull;
    #pragma unroll
    for (int o = 0; o < 4; ++o) {
        s0[o] = 0.f; s7[o] = 0.f;
        #pragma unroll
        for (int p = 0; p < 3; ++p) ao[o][p] = 0ull;
    }

    const float4 z4 = make_float4(0.f, 0.f, 0.f, 0.f);

#define COMPUTE(xa, xb, y0, y1, y2, y3)                                        \
    {                                                                          \
        u64 ypr[8];                                                            \
        ypr[0] = pk2(y0.x, y0.y); ypr[1] = pk2(y0.z, y0.w);                    \
        ypr[2] = pk2(y1.x, y1.y); ypr[3] = pk2(y1.z, y1.w);                    \
        ypr[4] = pk2(y2.x, y2.y); ypr[5] = pk2(y2.z, y2.w);                    \
        ypr[6] = pk2(y3.x, y3.y); ypr[7] = pk2(y3.z, y3.w);                    \
        u64 xe[4];                                                             \
        xe[0] = pk2(xa.x, xa.y); xe[1] = pk2(xa.z, xa.w);                      \
        xe[2] = pk2(xb.x, xb.y); xe[3] = pk2(xb.z, xb.w);                      \
        u64 xo[3];                                                             \
        xo[0] = pk2(xa.y, xa.z); xo[1] = pk2(xa.w, xb.x);                      \
        xo[2] = pk2(xb.y, xb.z);                                               \
        _Pragma("unroll")                                                      \
        for (int e = 0; e < 5; ++e)                                            \
            _Pragma("unroll")                                                  \
            for (int p = 0; p < 4; ++p) ffma2(ae[e][p], xe[p], ypr[p + e]);    \
        _Pragma("unroll")                                                      \
        for (int o = 0; o < 4; ++o) {                                          \
            _Pragma("unroll")                                                  \
            for (int p = 0; p < 3; ++p) ffma2(ao[o][p], xo[p], ypr[p + o + 1]);\
        }                                                                      \
        s0[0] = fmaf(xa.x, y0.y, s0[0]);                                       \
        s0[1] = fmaf(xa.x, y0.w, s0[1]);                                       \
        s0[2] = fmaf(xa.x, y1.y, s0[2]);                                       \
        s0[3] = fmaf(xa.x, y1.w, s0[3]);                                       \
        s7[0] = fmaf(xb.w, y2.x, s7[0]);                                       \
        s7[1] = fmaf(xb.w, y2.z, s7[1]);                                       \
        s7[2] = fmaf(xb.w, y3.x, s7[2]);                                       \
        s7[3] = fmaf(xb.w, y3.z, s7[3]);                                       \
    }

    // Prime buffer A with channel 0
    float4 Axa = *(const float4*)xp;
    float4 Axb = *(const float4*)(xp + 4);
    float4 Ay0 = first ? z4 : *(const float4*)yp;
    float4 Ay1 = *(const float4*)(yp + 4);
    float4 Ay2 = *(const float4*)(yp + 8);
    float4 Ay3 = last  ? z4 : *(const float4*)(yp + 12);

    #pragma unroll 1
    for (int c = 0; c < CH; c += 2) {
        // Load channel c+1 into B (always in-bounds: c+1 <= 255)
        const float* xn = xp + NPIX;
        const float* yn = yp + NPIX;
        float4 Bxa = *(const float4*)xn;
        float4 Bxb = *(const float4*)(xn + 4);
        float4 By0 = first ? z4 : *(const float4*)yn;
        float4 By1 = *(const float4*)(yn + 4);
        float4 By2 = *(const float4*)(yn + 8);
        float4 By3 = last  ? z4 : *(const float4*)(yn + 12);

        COMPUTE(Axa, Axb, Ay0, Ay1, Ay2, Ay3);

        // Load channel c+2 into A (clamped at the tail to stay in-bounds)
        const int adv = (c + 2 < CH) ? 2 * NPIX : 0;
        const float* xr = xp + adv;
        const float* yr = yp + adv;
        Axa = *(const float4*)xr;
        Axb = *(const float4*)(xr + 4);
        Ay0 = first ? z4 : *(const float4*)yr;
        Ay1 = *(const float4*)(yr + 4);
        Ay2 = *(const float4*)(yr + 8);
        Ay3 = last  ? z4 : *(const float4*)(yr + 12);

        COMPUTE(Bxa, Bxb, By0, By1, By2, By3);

        xp = xr; yp = yr;
    }
#undef COMPUTE

    const float sc = 1.0f / (float)CH;

    // Even oj = 2e
    #pragma unroll
    for (int e = 0; e < 5; ++e) {
        float v[8];
        #pragma unroll
        for (int p = 0; p < 4; ++p) upk2(ae[e][p], v[2 * p], v[2 * p + 1]);
        float* op = outp + (2 * e) * NPIX;
        *(float4*)op       = make_float4(v[0] * sc, v[1] * sc, v[2] * sc, v[3] * sc);
        *(float4*)(op + 4) = make_float4(v[4] * sc, v[5] * sc, v[6] * sc, v[7] * sc);
    }
    // Odd oj = 2o+1
    #pragma unroll
    for (int o = 0; o < 4; ++o) {
        float v[8];
        v[0] = s0[o];
        #pragma unroll
        for (int p = 0; p < 3; ++p) upk2(ao[o][p], v[2 * p + 1], v[2 * p + 2]);
        v[7] = s7[o];
        float* op = outp + (2 * o + 1) * NPIX;
        *(float4*)op       = make_float4(v[0] * sc, v[1] * sc, v[2] * sc, v[3] * sc);
        *(float4*)(op + 4) = make_float4(v[4] * sc, v[5] * sc, v[6] * sc, v[7] * sc);
    }
}

extern "C" void kernel_launch(void* const* d_in, const int* in_sizes, int n_in,
                              void* d_out, int out_size) {
    const float* x = (const float*)d_in[0];
    const float* y = (const float*)d_in[1];
    float* out = (float*)d_out;
    dim3 grid(HH / 2, BATCH);
    corr_kernel<<<grid, 144>>>(x, y, out);
}